// round 2
// baseline (speedup 1.0000x reference)
#include <cuda_runtime.h>
#include <math.h>

#define B_    32
#define IC    2048
#define OC    64
#define OD    32
#define ID    16
#define ITERS 5
#define OCD   (OC*OD)   // 2048

// Scratch (static device globals; no allocation at launch time).
__device__ float g_uhat[(size_t)B_ * IC * OCD];    // [b][i][o][d], 512 MB
__device__ float g_spart[(size_t)B_ * 256 * OCD];  // [b][slot][o*32+d], 64 MB
__device__ float g_V[B_ * OCD];                    // [b][o*32+d]

__global__ void init_V() {
    int idx = blockIdx.x * blockDim.x + threadIdx.x;
    if (idx < B_ * OCD) g_V[idx] = 0.f;
}

__device__ __forceinline__ float dot16(float4 w0, float4 w1, float4 w2, float4 w3,
                                       const float* xb) {
    float u = w0.x * xb[0];
    u = fmaf(w0.y, xb[1], u);
    u = fmaf(w0.z, xb[2], u);
    u = fmaf(w0.w, xb[3], u);
    u = fmaf(w1.x, xb[4], u);
    u = fmaf(w1.y, xb[5], u);
    u = fmaf(w1.z, xb[6], u);
    u = fmaf(w1.w, xb[7], u);
    u = fmaf(w2.x, xb[8], u);
    u = fmaf(w2.y, xb[9], u);
    u = fmaf(w2.z, xb[10], u);
    u = fmaf(w2.w, xb[11], u);
    u = fmaf(w3.x, xb[12], u);
    u = fmaf(w3.y, xb[13], u);
    u = fmaf(w3.z, xb[14], u);
    u = fmaf(w3.w, xb[15], u);
    return u;
}

// Pass A: u_hat[b,i,o,d] = sum_k W[i,o,d,k] * x[b,i,k]
// One CTA per i. Thread handles 8 (o,d) pairs (2 at a time), all 32 batches.
// Writes coalesced (lanes -> consecutive p = o*32+d).
__global__ __launch_bounds__(256) void uhat_kernel(const float* __restrict__ x,
                                                   const float* __restrict__ W) {
    int i = blockIdx.x;
    int t = threadIdx.x;
    __shared__ float xs[B_][ID];
    for (int idx = t; idx < B_ * ID; idx += 256) {
        int b = idx >> 4, k = idx & 15;
        xs[b][k] = x[((size_t)b * IC + i) * ID + k];
    }
    __syncthreads();

#pragma unroll
    for (int j = 0; j < 4; j++) {
        int p0 = t + 256 * (2 * j);
        int p1 = p0 + 256;
        const float4* w0p = (const float4*)(W + ((size_t)i * OCD + p0) * ID);
        const float4* w1p = (const float4*)(W + ((size_t)i * OCD + p1) * ID);
        float4 a0 = w0p[0], a1 = w0p[1], a2 = w0p[2], a3 = w0p[3];
        float4 b0 = w1p[0], b1 = w1p[1], b2 = w1p[2], b3 = w1p[3];
        for (int b = 0; b < B_; b++) {
            const float* xb = xs[b];
            float u0 = dot16(a0, a1, a2, a3, xb);
            float u1 = dot16(b0, b1, b2, b3, xb);
            size_t base = ((size_t)b * IC + i) * OCD;
            g_uhat[base + p0] = u0;
            g_uhat[base + p1] = u1;
        }
    }
}

// Routing pass: for each (b,i,d) softmax over o of u_hat*V, accumulate
// s_partial[o] = sum_i c*u_hat into per-warp slots (no atomics).
// CTA = (i-chunk of 64, b). Warp w handles i = chunk*64 + ii*8 + w; lane = d.
__global__ __launch_bounds__(256) void routing_kernel() {
    int chunk = blockIdx.x;
    int b = blockIdx.y;
    int t = threadIdx.x;
    __shared__ float Vs[OCD];  // V[b][o*32+d]
    for (int idx = t; idx < OCD; idx += 256) Vs[idx] = g_V[b * OCD + idx];
    __syncthreads();

    int w = t >> 5, d = t & 31;
    float acc[OC];
#pragma unroll
    for (int o = 0; o < OC; o++) acc[o] = 0.f;

    for (int ii = 0; ii < 8; ii++) {
        int i = chunk * 64 + ii * 8 + w;
        const float* up = g_uhat + ((size_t)b * IC + i) * OCD + d;
        float u[OC];
#pragma unroll
        for (int o = 0; o < OC; o++) u[o] = up[o * OD];  // 128B coalesced per o

        float m = -1e30f;
#pragma unroll
        for (int o = 0; o < OC; o++) m = fmaxf(m, u[o] * Vs[o * OD + d]);

        float Z = 0.f;
#pragma unroll
        for (int o = 0; o < OC; o++) {
            float e = __expf(u[o] * Vs[o * OD + d] - m);
            Z += e;
            u[o] *= e;  // u now holds u_hat * exp(logit - m)
        }
        float rZ = 1.0f / Z;
#pragma unroll
        for (int o = 0; o < OC; o++) acc[o] = fmaf(u[o], rZ, acc[o]);
    }

    int slot = chunk * 8 + w;  // 0..255
    float* sp = g_spart + ((size_t)b * 256 + slot) * OCD + d;
#pragma unroll
    for (int o = 0; o < OC; o++) sp[o * OD] = acc[o];
}

// Reduce partials over 256 slots, squash over d, update V (and write out on last iter).
__global__ __launch_bounds__(256) void update_kernel(float* __restrict__ out, int is_last) {
    int bo = blockIdx.x;       // 0..2047
    int b = bo >> 6, o = bo & 63;
    int t = threadIdx.x;
    int g = t >> 5, d = t & 31;

    float s = 0.f;
    for (int c = g; c < 256; c += 8)
        s += g_spart[((size_t)b * 256 + c) * OCD + o * OD + d];

    __shared__ float red[8][OD];
    red[g][d] = s;
    __syncthreads();

    if (t < 32) {
        float tot = 0.f;
#pragma unroll
        for (int gg = 0; gg < 8; gg++) tot += red[gg][d];
        // squash over d (warp butterfly for n2)
        float n2 = tot * tot;
#pragma unroll
        for (int k = 16; k > 0; k >>= 1) n2 += __shfl_xor_sync(0xffffffffu, n2, k);
        float factor = n2 / ((1.f + n2) * sqrtf(n2 + 1e-8f));
        float v = factor * tot;
        g_V[b * OCD + o * OD + d] += v;
        if (is_last) out[((size_t)b * OC + o) * OD + d] = v;
    }
}

extern "C" void kernel_launch(void* const* d_in, const int* in_sizes, int n_in,
                              void* d_out, int out_size) {
    // metadata order: x [32,2048,16], W [2048,64,32,16] — guard defensively by size.
    const float* x = (const float*)d_in[0];
    const float* W = (const float*)d_in[1];
    if (n_in >= 2 && in_sizes[0] > in_sizes[1]) {  // swapped?
        const float* tmp = x; x = W; W = tmp;
    }
    float* out = (float*)d_out;

    init_V<<<(B_ * OCD + 255) / 256, 256>>>();
    uhat_kernel<<<IC, 256>>>(x, W);
    for (int r = 0; r < ITERS; r++) {
        routing_kernel<<<dim3(32, B_), 256>>>();
        update_kernel<<<B_ * OC, 256>>>(out, r == ITERS - 1);
    }
}